// round 10
// baseline (speedup 1.0000x reference)
#include <cuda_runtime.h>
#include <cstdint>

#define N_RES 8192
#define N_IN  256
#define BATCH 16
#define NREP  16          // accumulator replicas

// Scratch (device globals — runtime allocation prohibited)
__device__ __align__(256) float g_ZTR[NREP][N_RES * BATCH]; // replicated accumulators [rep][row][b]
__device__ __align__(256) float g_ST[N_RES * BATCH];        // state^T, [col][b]
__device__ __align__(256) float g_XT[N_IN * BATCH];         // x^T, [col][b]

__device__ __forceinline__ void red_add_v4(float* addr, float a, float b, float c, float d) {
    asm volatile("red.global.add.v4.f32 [%0], {%1, %2, %3, %4};"
                 :: "l"(addr), "f"(a), "f"(b), "f"(c), "f"(d)
                 : "memory");
}

// 1) prep: smem-tiled transpose (coalesced reads AND writes) + zero replicas.
//    Blocks 0..127 each transpose a 16(b) x 64(r) tile of state into ST.
//    Block 128 handles x -> XT. All blocks zero a slice of ZTR.
__global__ void prep_kernel(const float* __restrict__ state,
                            const float* __restrict__ x) {
    __shared__ float tile[BATCH][65];   // padded: <=2-way bank conflicts
    int t   = threadIdx.x;              // 256 threads
    int blk = blockIdx.x;

    if (blk < 128) {
        int r_base = blk * 64;
        // load: 1024 elements, 4 per thread; coalesced 256B rows of state
#pragma unroll
        for (int it = 0; it < 4; it++) {
            int idx = it * 256 + t;
            int bb  = idx >> 6;         // 0..15
            int j   = idx & 63;         // 0..63
            tile[bb][j] = state[bb * N_RES + r_base + j];
        }
        __syncthreads();
        // store: thread t writes quarter q of ST row (r_base + rl) as float4
        int rl = t >> 2;                // 0..63
        int q  = t & 3;                 // 0..3
        float4 v = make_float4(tile[4 * q + 0][rl], tile[4 * q + 1][rl],
                               tile[4 * q + 2][rl], tile[4 * q + 3][rl]);
        reinterpret_cast<float4*>(g_ST)[(r_base + rl) * 4 + q] = v;
    } else if (blk == 128) {
        // x -> XT: 4096 elements, 16 per thread (strided writes, tiny)
        for (int idx = t; idx < N_IN * BATCH; idx += 256) {
            int b = idx >> 8;
            int c = idx & (N_IN - 1);
            g_XT[c * BATCH + b] = x[idx];
        }
    }

    // zero replicas (all blocks, grid-stride over 2M float4s)
    float4* z = reinterpret_cast<float4*>(&g_ZTR[0][0]);
    int total4 = NREP * N_RES * BATCH / 4;
    int gt = blk * 256 + t;
    for (int i = gt; i < total4; i += gridDim.x * 256)
        z[i] = make_float4(0.f, 0.f, 0.f, 0.f);
}

// 2) combined SpMM: first in_blocks handle the input matrix (gather from XT),
//    remaining blocks handle the reservoir matrix (gather from ST).
//    4 lanes per nnz: lane quarter q owns batch slice [4q, 4q+4).
__global__ void spmm_all_kernel(const float* __restrict__ res_vals,
                                const int*   __restrict__ res_rows,
                                const int*   __restrict__ res_cols, int nnz_res,
                                const float* __restrict__ in_vals,
                                const int*   __restrict__ in_rows,
                                const int*   __restrict__ in_cols, int nnz_in,
                                int in_blocks) {
    const float* vals;
    const int*   rows;
    const int*   cols;
    const float* src_mat;
    int nnz, t;

    if (blockIdx.x < in_blocks) {
        vals = in_vals; rows = in_rows; cols = in_cols;
        src_mat = g_XT; nnz = nnz_in;
        t = blockIdx.x * blockDim.x + threadIdx.x;
    } else {
        vals = res_vals; rows = res_rows; cols = res_cols;
        src_mat = g_ST; nnz = nnz_res;
        t = (blockIdx.x - in_blocks) * blockDim.x + threadIdx.x;
    }

    int i = t >> 2;            // nnz index (8 nnz per warp)
    int q = t & 3;             // batch quarter
    if (i >= nnz) return;
    int rep = (t >> 5) & (NREP - 1);

    float val = vals[i];       // quartet-redundant, sector-coalesced
    int   row = rows[i];
    int   col = cols[i];

    float4 s = __ldg(reinterpret_cast<const float4*>(src_mat) + col * 4 + q);
    float* dst = &g_ZTR[rep][row * BATCH + q * 4];
    red_add_v4(dst, val * s.x, val * s.y, val * s.z, val * s.w);
}

// 3) reduce replicas + bias, erf, transposed write
__global__ void finish_kernel(const float* __restrict__ bias,
                              float* __restrict__ out) {
    int t = blockIdx.x * blockDim.x + threadIdx.x;
    if (t >= N_RES * BATCH) return;
    int r = t >> 4;
    int b = t & (BATCH - 1);

    float z = bias[r];
#pragma unroll
    for (int rep = 0; rep < NREP; rep++)
        z += g_ZTR[rep][t];
    out[b * N_RES + r] = erff(z);
}

extern "C" void kernel_launch(void* const* d_in, const int* in_sizes, int n_in,
                              void* d_out, int out_size) {
    const float* state    = (const float*)d_in[0];
    const float* x        = (const float*)d_in[1];
    const float* res_vals = (const float*)d_in[2];
    const int*   res_rows = (const int*)  d_in[3];
    const int*   res_cols = (const int*)  d_in[4];
    const float* res_bias = (const float*)d_in[5];
    const float* in_vals  = (const float*)d_in[6];
    const int*   in_rows  = (const int*)  d_in[7];
    const int*   in_cols  = (const int*)  d_in[8];
    float* out = (float*)d_out;

    int nnz_res = in_sizes[2];
    int nnz_in  = in_sizes[6];

    const int TPB = 256;

    prep_kernel<<<1024, TPB>>>(state, x);   // 128 transpose blocks + zeroing spread

    int in_blocks  = (int)(((long long)nnz_in  * 4 + TPB - 1) / TPB);
    int res_blocks = (int)(((long long)nnz_res * 4 + TPB - 1) / TPB);
    spmm_all_kernel<<<in_blocks + res_blocks, TPB>>>(
        res_vals, res_rows, res_cols, nnz_res,
        in_vals, in_rows, in_cols, nnz_in, in_blocks);

    finish_kernel<<<(N_RES * BATCH + TPB - 1) / TPB, TPB>>>(res_bias, out);
}